// round 4
// baseline (speedup 1.0000x reference)
#include <cuda_runtime.h>
#include <cstdint>

// Problem dims
#define B_  16
#define T_  512
#define E_  4096
#define H_  8
#define HD_ 512
#define NBH 128            // B_*H_
#define QSZ 33554432       // B_*H_*T_*HD_ = B_*T_*E_

// GEMM tiling
#define BM 128
#define BN 128
#define BK 32
#define AST 36    // A shared row stride (floats): bank = 4g+t (conflict-free frags)
#define BST 136   // B shared row stride (floats): bank = 8t+g (conflict-free frags)

// Scratch (device globals: allocation-free per harness rules)
__device__ float gQ[QSZ];
__device__ float gK[QSZ];
__device__ float gV[QSZ];
__device__ float gS[QSZ];   // scores / probabilities [B,H,T,T]
__device__ float gY[QSZ];   // concatenated attention output [B,T,E]

// ---------------------------------------------------------------------------
// helpers
// ---------------------------------------------------------------------------
__device__ __forceinline__ uint32_t f2tf(float f) {
    uint32_t u;
    asm("cvt.rna.tf32.f32 %0, %1;" : "=r"(u) : "f"(f));
    return u;
}

__device__ __forceinline__ void mma8(float* c, const uint32_t* a, const uint32_t* b) {
    asm volatile(
        "mma.sync.aligned.m16n8k8.row.col.f32.tf32.tf32.f32 "
        "{%0,%1,%2,%3},{%4,%5,%6,%7},{%8,%9},{%0,%1,%2,%3};\n"
        : "+f"(c[0]), "+f"(c[1]), "+f"(c[2]), "+f"(c[3])
        : "r"(a[0]), "r"(a[1]), "r"(a[2]), "r"(a[3]), "r"(b[0]), "r"(b[1]));
}

// ---- global tile loads (register staging) ----
__device__ __forceinline__ void ldgA(const float* __restrict__ Ag, int lda,
                                     float4* v, int tid) {
#pragma unroll
    for (int t = 0; t < 4; t++) {
        int idx = t * 256 + tid;
        int row = idx >> 3, kq = idx & 7;        // 8 float4 per 32-float row
        v[t] = *reinterpret_cast<const float4*>(Ag + (size_t)row * lda + kq * 4);
    }
}

__device__ __forceinline__ void ldgBn(const float* __restrict__ Bg, int ldb,
                                      float4* v, int tid) {
#pragma unroll
    for (int t = 0; t < 4; t++) {
        int idx = t * 256 + tid;
        int k = idx >> 5, nq = idx & 31;         // 32 float4 per 128-float row
        v[t] = *reinterpret_cast<const float4*>(Bg + (size_t)k * ldb + nq * 4);
    }
}

__device__ __forceinline__ void ldgBt(const float* __restrict__ Bg, int ldb,
                                      float4* v, int tid) {
#pragma unroll
    for (int t = 0; t < 4; t++) {
        int idx = t * 256 + tid;
        int n = idx >> 3, kq = idx & 7;          // row n of K-matrix, 4 k's
        v[t] = *reinterpret_cast<const float4*>(Bg + (size_t)n * ldb + kq * 4);
    }
}

// ---- shared tile stores (tf32-converted) ----
__device__ __forceinline__ void stsA(uint32_t* As, const float4* v, int tid) {
#pragma unroll
    for (int t = 0; t < 4; t++) {
        int idx = t * 256 + tid;
        int row = idx >> 3, kq = idx & 7;
        uint4 u;
        u.x = f2tf(v[t].x); u.y = f2tf(v[t].y); u.z = f2tf(v[t].z); u.w = f2tf(v[t].w);
        *reinterpret_cast<uint4*>(As + row * AST + kq * 4) = u;
    }
}

__device__ __forceinline__ void stsBn(uint32_t* Bs, const float4* v, int tid) {
#pragma unroll
    for (int t = 0; t < 4; t++) {
        int idx = t * 256 + tid;
        int k = idx >> 5, nq = idx & 31;
        uint4 u;
        u.x = f2tf(v[t].x); u.y = f2tf(v[t].y); u.z = f2tf(v[t].z); u.w = f2tf(v[t].w);
        *reinterpret_cast<uint4*>(Bs + k * BST + nq * 4) = u;
    }
}

__device__ __forceinline__ void stsBt(uint32_t* Bs, const float4* v, int tid) {
#pragma unroll
    for (int t = 0; t < 4; t++) {
        int idx = t * 256 + tid;
        int n = idx >> 3, kq = idx & 7;
        int k = kq * 4;
        Bs[(k + 0) * BST + n] = f2tf(v[t].x);
        Bs[(k + 1) * BST + n] = f2tf(v[t].y);
        Bs[(k + 2) * BST + n] = f2tf(v[t].z);
        Bs[(k + 3) * BST + n] = f2tf(v[t].w);
    }
}

// ---- mma compute on one BMxBK / BKxBN shared tile pair ----
__device__ __forceinline__ void compute_tile(const uint32_t* As, const uint32_t* Bs,
                                             float (&acc)[4][4][4],
                                             int lane, int wm, int wn) {
    int g = lane >> 2, t = lane & 3;
#pragma unroll
    for (int s = 0; s < 4; s++) {                // k-steps of 8
        uint32_t a[4][4];
        uint32_t b[4][2];
#pragma unroll
        for (int i = 0; i < 4; i++) {
            const uint32_t* ap = As + ((wm * 4 + i) * 16 + g) * AST + s * 8 + t;
            a[i][0] = ap[0];
            a[i][1] = ap[8 * AST];
            a[i][2] = ap[4];
            a[i][3] = ap[8 * AST + 4];
        }
#pragma unroll
        for (int j = 0; j < 4; j++) {
            const uint32_t* bp = Bs + (s * 8 + t) * BST + (wn * 4 + j) * 8 + g;
            b[j][0] = bp[0];
            b[j][1] = bp[4 * BST];
        }
#pragma unroll
        for (int i = 0; i < 4; i++)
#pragma unroll
            for (int j = 0; j < 4; j++)
                mma8(acc[i][j], a[i], b[j]);
    }
}

// ---- main GEMM loop (register-prefetch double buffered) ----
template <bool TRANSB>
__device__ __forceinline__ void gemm_main(const float* __restrict__ Ag, int lda,
                                          const float* __restrict__ Bg, int ldb,
                                          int nkt, uint32_t* As, uint32_t* Bs,
                                          float (&acc)[4][4][4],
                                          int tid, int lane, int wm, int wn) {
    float4 av[4], bv[4];
    ldgA(Ag, lda, av, tid);
    if (TRANSB) ldgBt(Bg, ldb, bv, tid); else ldgBn(Bg, ldb, bv, tid);
    stsA(As, av, tid);
    if (TRANSB) stsBt(Bs, bv, tid); else stsBn(Bs, bv, tid);
    __syncthreads();

    for (int kt = 0; kt < nkt; kt++) {
        bool more = (kt + 1 < nkt);
        if (more) {
            ldgA(Ag + (kt + 1) * BK, lda, av, tid);
            if (TRANSB) ldgBt(Bg + (kt + 1) * BK, ldb, bv, tid);
            else        ldgBn(Bg + (size_t)(kt + 1) * BK * ldb, ldb, bv, tid);
        }
        compute_tile(As, Bs, acc, lane, wm, wn);
        __syncthreads();
        if (more) {
            stsA(As, av, tid);
            if (TRANSB) stsBt(Bs, bv, tid); else stsBn(Bs, bv, tid);
            __syncthreads();
        }
    }
}

__device__ __forceinline__ void zero_acc(float (&acc)[4][4][4]) {
#pragma unroll
    for (int i = 0; i < 4; i++)
#pragma unroll
        for (int j = 0; j < 4; j++)
#pragma unroll
            for (int k = 0; k < 4; k++) acc[i][j][k] = 0.f;
}

__device__ __forceinline__ void store_acc(float* C, int ldc,
                                          const float (&acc)[4][4][4],
                                          int lane, int wm, int wn) {
    int g = lane >> 2, t = lane & 3;
#pragma unroll
    for (int i = 0; i < 4; i++)
#pragma unroll
        for (int j = 0; j < 4; j++) {
            int r0 = (wm * 4 + i) * 16 + g;
            int c0 = (wn * 4 + j) * 8 + t * 2;
            float* p = C + (size_t)r0 * ldc + c0;
            p[0] = acc[i][j][0];
            p[1] = acc[i][j][1];
            p[(size_t)8 * ldc]     = acc[i][j][2];
            p[(size_t)8 * ldc + 1] = acc[i][j][3];
        }
}

// ---------------------------------------------------------------------------
// Kernel 1: fused QKV projection. C[8192,12288] = data[8192,4096] x [Wq|Wk|Wv]
// ---------------------------------------------------------------------------
__global__ __launch_bounds__(256) void k_qkv(const float* __restrict__ data,
                                             const float* __restrict__ Wq,
                                             const float* __restrict__ Wk,
                                             const float* __restrict__ Wv) {
    __shared__ __align__(16) uint32_t As[BM * AST];
    __shared__ __align__(16) uint32_t Bs[BK * BST];
    int tid = threadIdx.x, lane = tid & 31, wid = tid >> 5;
    int wm = wid >> 2, wn = wid & 3;

    int n0 = blockIdx.x * BN;
    int m0 = blockIdx.y * BM;
    int which = n0 >> 12;          // 0:q 1:k 2:v
    int rem = n0 & 4095;
    int h = rem >> 9, d0 = rem & 511;
    const float* W = (which == 0) ? Wq : (which == 1) ? Wk : Wv;
    const float* Bg = W + (size_t)h * E_ * HD_ + d0;      // ldb = HD_
    const float* Ag = data + (size_t)m0 * E_;

    float acc[4][4][4];
    zero_acc(acc);
    gemm_main<false>(Ag, E_, Bg, HD_, E_ / BK, As, Bs, acc, tid, lane, wm, wn);

    float* ob = (which == 0) ? gQ : (which == 1) ? gK : gV;
    int b = m0 >> 9, t0 = m0 & 511;
    float* C = ob + ((size_t)(b * H_ + h) * T_ + t0) * HD_ + d0;
    store_acc(C, HD_, acc, lane, wm, wn);
}

// ---------------------------------------------------------------------------
// Kernel 2: scores S = Q K^T / sqrt(E), causal (block-skipped + masked store)
// ---------------------------------------------------------------------------
__global__ __launch_bounds__(256) void k_scores() {
    int n0 = blockIdx.x * BN;
    int m0 = blockIdx.y * BM;
    if (n0 > m0) return;                         // fully masked tile
    int z = blockIdx.z;

    __shared__ __align__(16) uint32_t As[BM * AST];
    __shared__ __align__(16) uint32_t Bs[BK * BST];
    int tid = threadIdx.x, lane = tid & 31, wid = tid >> 5;
    int wm = wid >> 2, wn = wid & 3;

    const float* Ag = gQ + (size_t)z * T_ * HD_ + (size_t)m0 * HD_;
    const float* Bg = gK + (size_t)z * T_ * HD_ + (size_t)n0 * HD_;  // transposed-B

    float acc[4][4][4];
    zero_acc(acc);
    gemm_main<true>(Ag, HD_, Bg, HD_, HD_ / BK, As, Bs, acc, tid, lane, wm, wn);

    const float sc = 0.015625f;                  // 1/sqrt(4096)
    float* C = gS + (size_t)z * T_ * T_ + (size_t)m0 * T_ + n0;
    int g = lane >> 2, t = lane & 3;
#pragma unroll
    for (int i = 0; i < 4; i++)
#pragma unroll
        for (int j = 0; j < 4; j++) {
            int r0 = (wm * 4 + i) * 16 + g;
            int c0 = (wn * 4 + j) * 8 + t * 2;
            int gr = m0 + r0, gc = n0 + c0;
            float* p = C + (size_t)r0 * T_ + c0;
            if (gc     <= gr)     p[0]            = acc[i][j][0] * sc;
            if (gc + 1 <= gr)     p[1]            = acc[i][j][1] * sc;
            if (gc     <= gr + 8) p[8 * T_]       = acc[i][j][2] * sc;
            if (gc + 1 <= gr + 8) p[8 * T_ + 1]   = acc[i][j][3] * sc;
        }
}

// ---------------------------------------------------------------------------
// Kernel 3: causal row softmax; zero-fills masked tail (lets PV over-read)
// ---------------------------------------------------------------------------
__global__ __launch_bounds__(128) void k_softmax() {
    int r = blockIdx.x;
    int z = blockIdx.y;
    float* row = gS + (size_t)z * T_ * T_ + (size_t)r * T_;
    int n = r + 1;
    int tid = threadIdx.x;
    __shared__ float sm[4];

    float v = -3.4e38f;
    for (int i = tid; i < n; i += 128) v = fmaxf(v, row[i]);
#pragma unroll
    for (int o = 16; o; o >>= 1) v = fmaxf(v, __shfl_xor_sync(0xffffffffu, v, o));
    if ((tid & 31) == 0) sm[tid >> 5] = v;
    __syncthreads();
    float M = fmaxf(fmaxf(sm[0], sm[1]), fmaxf(sm[2], sm[3]));
    __syncthreads();

    float s = 0.f;
    for (int i = tid; i < n; i += 128) {
        float e = __expf(row[i] - M);
        row[i] = e;
        s += e;
    }
#pragma unroll
    for (int o = 16; o; o >>= 1) s += __shfl_xor_sync(0xffffffffu, s, o);
    if ((tid & 31) == 0) sm[tid >> 5] = s;
    __syncthreads();
    float inv = 1.f / (sm[0] + sm[1] + sm[2] + sm[3]);

    for (int i = tid; i < T_; i += 128)
        row[i] = (i < n) ? row[i] * inv : 0.f;
}

// ---------------------------------------------------------------------------
// Kernel 4: O = P V  (K-loop truncated by causality), writes concat layout gY
// ---------------------------------------------------------------------------
__global__ __launch_bounds__(256) void k_av() {
    __shared__ __align__(16) uint32_t As[BM * AST];
    __shared__ __align__(16) uint32_t Bs[BK * BST];
    int tid = threadIdx.x, lane = tid & 31, wid = tid >> 5;
    int wm = wid >> 2, wn = wid & 3;

    int n0 = blockIdx.x * BN;      // d0
    int m0 = blockIdx.y * BM;      // t0
    int z = blockIdx.z;
    int b = z >> 3, h = z & 7;

    const float* Ag = gS + (size_t)z * T_ * T_ + (size_t)m0 * T_;
    const float* Bg = gV + (size_t)z * T_ * HD_ + n0;
    int nkt = (m0 + BM) / BK;      // causal truncation

    float acc[4][4][4];
    zero_acc(acc);
    gemm_main<false>(Ag, T_, Bg, HD_, nkt, As, Bs, acc, tid, lane, wm, wn);

    float* C = gY + ((size_t)b * T_ + m0) * E_ + h * HD_ + n0;
    store_acc(C, E_, acc, lane, wm, wn);
}

// ---------------------------------------------------------------------------
// Kernel 5: out = Y @ Wo + bo
// ---------------------------------------------------------------------------
__global__ __launch_bounds__(256) void k_out(const float* __restrict__ Wo,
                                             const float* __restrict__ bo,
                                             float* __restrict__ out) {
    __shared__ __align__(16) uint32_t As[BM * AST];
    __shared__ __align__(16) uint32_t Bs[BK * BST];
    int tid = threadIdx.x, lane = tid & 31, wid = tid >> 5;
    int wm = wid >> 2, wn = wid & 3;

    int n0 = blockIdx.x * BN;
    int m0 = blockIdx.y * BM;

    const float* Ag = gY + (size_t)m0 * E_;
    const float* Bg = Wo + n0;

    float acc[4][4][4];
    zero_acc(acc);
    gemm_main<false>(Ag, E_, Bg, E_, E_ / BK, As, Bs, acc, tid, lane, wm, wn);

    float* C = out + (size_t)m0 * E_ + n0;
    int g = lane >> 2, t = lane & 3;
#pragma unroll
    for (int i = 0; i < 4; i++)
#pragma unroll
        for (int j = 0; j < 4; j++) {
            int r0 = (wm * 4 + i) * 16 + g;
            int c0 = (wn * 4 + j) * 8 + t * 2;
            float b0 = bo[n0 + c0], b1 = bo[n0 + c0 + 1];
            float* p = C + (size_t)r0 * E_ + c0;
            p[0]           = acc[i][j][0] + b0;
            p[1]           = acc[i][j][1] + b1;
            p[8 * E_]      = acc[i][j][2] + b0;
            p[8 * E_ + 1]  = acc[i][j][3] + b1;
        }
}

// ---------------------------------------------------------------------------
extern "C" void kernel_launch(void* const* d_in, const int* in_sizes, int n_in,
                              void* d_out, int out_size) {
    const float* data = (const float*)d_in[0];
    const float* Wq   = (const float*)d_in[1];
    const float* Wk   = (const float*)d_in[2];
    const float* Wv   = (const float*)d_in[3];
    const float* Wo   = (const float*)d_in[4];
    const float* bo   = (const float*)d_in[5];
    float* out = (float*)d_out;

    k_qkv   <<<dim3(96, 64),      256>>>(data, Wq, Wk, Wv);
    k_scores<<<dim3(4, 4, NBH),   256>>>();
    k_softmax<<<dim3(T_, NBH),    128>>>();
    k_av    <<<dim3(4, 4, NBH),   256>>>();
    k_out   <<<dim3(32, 64),      256>>>(Wo, bo, out);
}

// round 6
// speedup vs baseline: 1.0259x; 1.0259x over previous
#include <cuda_runtime.h>
#include <cstdint>

// Problem dims
#define B_  16
#define T_  512
#define E_  4096
#define H_  8
#define HD_ 512
#define NBH 128            // B_*H_
#define QSZ 33554432       // B_*H_*T_*HD_ = B_*T_*E_

// GEMM tiling
#define BM 128
#define BN 128
#define BK 32
#define AST 36    // A shared row stride (floats): bank = 4g+t (conflict-free frags)
#define BST 136   // B shared row stride (floats): bank = 8t+g (conflict-free frags)
#define ASZ (BM * AST)           // 4608 u32 per A buffer
#define BSZ (BK * BST)           // 4352 u32 per B buffer
#define SMEM_DB ((2 * ASZ + 2 * BSZ) * 4)   // 71680 bytes (double-buffered)

// Scratch (device globals: allocation-free per harness rules)
__device__ float gQ[QSZ];
__device__ float gK[QSZ];
__device__ float gV[QSZ];
__device__ float gS[QSZ];   // scores / probabilities [B,H,T,T]
__device__ float gY[QSZ];   // concatenated attention output [B,T,E]

// ---------------------------------------------------------------------------
// helpers
// ---------------------------------------------------------------------------
__device__ __forceinline__ uint32_t f2tf(float f) {
    uint32_t u;
    asm("cvt.rna.tf32.f32 %0, %1;" : "=r"(u) : "f"(f));
    return u;
}

__device__ __forceinline__ void mma8(float* c, const uint32_t* a, const uint32_t* b) {
    asm volatile(
        "mma.sync.aligned.m16n8k8.row.col.f32.tf32.tf32.f32 "
        "{%0,%1,%2,%3},{%4,%5,%6,%7},{%8,%9},{%0,%1,%2,%3};\n"
        : "+f"(c[0]), "+f"(c[1]), "+f"(c[2]), "+f"(c[3])
        : "r"(a[0]), "r"(a[1]), "r"(a[2]), "r"(a[3]), "r"(b[0]), "r"(b[1]));
}

// ---- global tile loads (register staging) ----
__device__ __forceinline__ void ldgA(const float* __restrict__ Ag, int lda,
                                     float4* v, int tid) {
#pragma unroll
    for (int t = 0; t < 4; t++) {
        int idx = t * 256 + tid;
        int row = idx >> 3, kq = idx & 7;        // 8 float4 per 32-float row
        v[t] = *reinterpret_cast<const float4*>(Ag + (size_t)row * lda + kq * 4);
    }
}

__device__ __forceinline__ void ldgBn(const float* __restrict__ Bg, int ldb,
                                      float4* v, int tid) {
#pragma unroll
    for (int t = 0; t < 4; t++) {
        int idx = t * 256 + tid;
        int k = idx >> 5, nq = idx & 31;         // 32 float4 per 128-float row
        v[t] = *reinterpret_cast<const float4*>(Bg + (size_t)k * ldb + nq * 4);
    }
}

__device__ __forceinline__ void ldgBt(const float* __restrict__ Bg, int ldb,
                                      float4* v, int tid) {
#pragma unroll
    for (int t = 0; t < 4; t++) {
        int idx = t * 256 + tid;
        int n = idx >> 3, kq = idx & 7;          // row n of K-matrix, 4 k's
        v[t] = *reinterpret_cast<const float4*>(Bg + (size_t)n * ldb + kq * 4);
    }
}

// ---- shared tile stores (tf32-converted) ----
__device__ __forceinline__ void stsA(uint32_t* As, const float4* v, int tid) {
#pragma unroll
    for (int t = 0; t < 4; t++) {
        int idx = t * 256 + tid;
        int row = idx >> 3, kq = idx & 7;
        uint4 u;
        u.x = f2tf(v[t].x); u.y = f2tf(v[t].y); u.z = f2tf(v[t].z); u.w = f2tf(v[t].w);
        *reinterpret_cast<uint4*>(As + row * AST + kq * 4) = u;
    }
}

__device__ __forceinline__ void stsBn(uint32_t* Bs, const float4* v, int tid) {
#pragma unroll
    for (int t = 0; t < 4; t++) {
        int idx = t * 256 + tid;
        int k = idx >> 5, nq = idx & 31;
        uint4 u;
        u.x = f2tf(v[t].x); u.y = f2tf(v[t].y); u.z = f2tf(v[t].z); u.w = f2tf(v[t].w);
        *reinterpret_cast<uint4*>(Bs + k * BST + nq * 4) = u;
    }
}

__device__ __forceinline__ void stsBt(uint32_t* Bs, const float4* v, int tid) {
#pragma unroll
    for (int t = 0; t < 4; t++) {
        int idx = t * 256 + tid;
        int n = idx >> 3, kq = idx & 7;
        int k = kq * 4;
        Bs[(k + 0) * BST + n] = f2tf(v[t].x);
        Bs[(k + 1) * BST + n] = f2tf(v[t].y);
        Bs[(k + 2) * BST + n] = f2tf(v[t].z);
        Bs[(k + 3) * BST + n] = f2tf(v[t].w);
    }
}

// ---- mma compute on one BMxBK / BKxBN shared tile pair ----
__device__ __forceinline__ void compute_tile(const uint32_t* As, const uint32_t* Bs,
                                             float (&acc)[4][4][4],
                                             int lane, int wm, int wn) {
    int g = lane >> 2, t = lane & 3;
#pragma unroll
    for (int s = 0; s < 4; s++) {                // k-steps of 8
        uint32_t a[4][4];
        uint32_t b[4][2];
#pragma unroll
        for (int i = 0; i < 4; i++) {
            const uint32_t* ap = As + ((wm * 4 + i) * 16 + g) * AST + s * 8 + t;
            a[i][0] = ap[0];
            a[i][1] = ap[8 * AST];
            a[i][2] = ap[4];
            a[i][3] = ap[8 * AST + 4];
        }
#pragma unroll
        for (int j = 0; j < 4; j++) {
            const uint32_t* bp = Bs + (s * 8 + t) * BST + (wn * 4 + j) * 8 + g;
            b[j][0] = bp[0];
            b[j][1] = bp[4 * BST];
        }
#pragma unroll
        for (int i = 0; i < 4; i++)
#pragma unroll
            for (int j = 0; j < 4; j++)
                mma8(acc[i][j], a[i], b[j]);
    }
}

// ---- main GEMM loop: SMEM double-buffered, ONE __syncthreads per K-tile ----
// Safety: during iter kt we write buffer nb=(kt+1)&1 while computing on cb.
// nb's previous contents were consumed in iter kt-1; the barrier at the end of
// iter kt-1 proved every warp finished that compute, so the overwrite is safe.
template <bool TRANSB>
__device__ __forceinline__ void gemm_main(const float* __restrict__ Ag, int lda,
                                          const float* __restrict__ Bg, int ldb,
                                          int nkt, uint32_t* As, uint32_t* Bs,
                                          float (&acc)[4][4][4],
                                          int tid, int lane, int wm, int wn) {
    float4 av[4], bv[4];
    ldgA(Ag, lda, av, tid);
    if (TRANSB) ldgBt(Bg, ldb, bv, tid); else ldgBn(Bg, ldb, bv, tid);
    stsA(As, av, tid);
    if (TRANSB) stsBt(Bs, bv, tid); else stsBn(Bs, bv, tid);
    __syncthreads();

    for (int kt = 0; kt < nkt; kt++) {
        int cb = kt & 1, nb = cb ^ 1;
        bool more = (kt + 1 < nkt);
        if (more) {
            ldgA(Ag + (kt + 1) * BK, lda, av, tid);
            if (TRANSB) ldgBt(Bg + (kt + 1) * BK, ldb, bv, tid);
            else        ldgBn(Bg + (size_t)(kt + 1) * BK * ldb, ldb, bv, tid);
        }
        compute_tile(As + cb * ASZ, Bs + cb * BSZ, acc, lane, wm, wn);
        if (more) {
            stsA(As + nb * ASZ, av, tid);
            if (TRANSB) stsBt(Bs + nb * BSZ, bv, tid);
            else        stsBn(Bs + nb * BSZ, bv, tid);
            __syncthreads();
        }
    }
}

__device__ __forceinline__ void zero_acc(float (&acc)[4][4][4]) {
#pragma unroll
    for (int i = 0; i < 4; i++)
#pragma unroll
        for (int j = 0; j < 4; j++)
#pragma unroll
            for (int k = 0; k < 4; k++) acc[i][j][k] = 0.f;
}

__device__ __forceinline__ void store_acc(float* C, int ldc,
                                          const float (&acc)[4][4][4],
                                          int lane, int wm, int wn) {
    int g = lane >> 2, t = lane & 3;
#pragma unroll
    for (int i = 0; i < 4; i++)
#pragma unroll
        for (int j = 0; j < 4; j++) {
            int r0 = (wm * 4 + i) * 16 + g;
            int c0 = (wn * 4 + j) * 8 + t * 2;
            float* p = C + (size_t)r0 * ldc + c0;
            p[0] = acc[i][j][0];
            p[1] = acc[i][j][1];
            p[(size_t)8 * ldc]     = acc[i][j][2];
            p[(size_t)8 * ldc + 1] = acc[i][j][3];
        }
}

// ---------------------------------------------------------------------------
// Kernel 1: fused QKV projection. C[8192,12288] = data[8192,4096] x [Wq|Wk|Wv]
// ---------------------------------------------------------------------------
__global__ __launch_bounds__(256) void k_qkv(const float* __restrict__ data,
                                             const float* __restrict__ Wq,
                                             const float* __restrict__ Wk,
                                             const float* __restrict__ Wv) {
    extern __shared__ __align__(16) uint32_t smem[];
    uint32_t* As = smem;
    uint32_t* Bs = smem + 2 * ASZ;
    int tid = threadIdx.x, lane = tid & 31, wid = tid >> 5;
    int wm = wid >> 2, wn = wid & 3;

    int n0 = blockIdx.x * BN;
    int m0 = blockIdx.y * BM;
    int which = n0 >> 12;          // 0:q 1:k 2:v
    int rem = n0 & 4095;
    int h = rem >> 9, d0 = rem & 511;
    const float* W = (which == 0) ? Wq : (which == 1) ? Wk : Wv;
    const float* Bg = W + (size_t)h * E_ * HD_ + d0;      // ldb = HD_
    const float* Ag = data + (size_t)m0 * E_;

    float acc[4][4][4];
    zero_acc(acc);
    gemm_main<false>(Ag, E_, Bg, HD_, E_ / BK, As, Bs, acc, tid, lane, wm, wn);

    float* ob = (which == 0) ? gQ : (which == 1) ? gK : gV;
    int b = m0 >> 9, t0 = m0 & 511;
    float* C = ob + ((size_t)(b * H_ + h) * T_ + t0) * HD_ + d0;
    store_acc(C, HD_, acc, lane, wm, wn);
}

// ---------------------------------------------------------------------------
// Kernel 2: scores S = Q K^T / sqrt(E), causal (block-skipped + masked store)
// ---------------------------------------------------------------------------
__global__ __launch_bounds__(256) void k_scores() {
    int n0 = blockIdx.x * BN;
    int m0 = blockIdx.y * BM;
    if (n0 > m0) return;                         // fully masked tile
    int z = blockIdx.z;

    extern __shared__ __align__(16) uint32_t smem[];
    uint32_t* As = smem;
    uint32_t* Bs = smem + 2 * ASZ;
    int tid = threadIdx.x, lane = tid & 31, wid = tid >> 5;
    int wm = wid >> 2, wn = wid & 3;

    const float* Ag = gQ + (size_t)z * T_ * HD_ + (size_t)m0 * HD_;
    const float* Bg = gK + (size_t)z * T_ * HD_ + (size_t)n0 * HD_;  // transposed-B

    float acc[4][4][4];
    zero_acc(acc);
    gemm_main<true>(Ag, HD_, Bg, HD_, HD_ / BK, As, Bs, acc, tid, lane, wm, wn);

    const float sc = 0.015625f;                  // 1/sqrt(4096)
    float* C = gS + (size_t)z * T_ * T_ + (size_t)m0 * T_ + n0;
    int g = lane >> 2, t = lane & 3;
#pragma unroll
    for (int i = 0; i < 4; i++)
#pragma unroll
        for (int j = 0; j < 4; j++) {
            int r0 = (wm * 4 + i) * 16 + g;
            int c0 = (wn * 4 + j) * 8 + t * 2;
            int gr = m0 + r0, gc = n0 + c0;
            float* p = C + (size_t)r0 * T_ + c0;
            if (gc     <= gr)     p[0]            = acc[i][j][0] * sc;
            if (gc + 1 <= gr)     p[1]            = acc[i][j][1] * sc;
            if (gc     <= gr + 8) p[8 * T_]       = acc[i][j][2] * sc;
            if (gc + 1 <= gr + 8) p[8 * T_ + 1]   = acc[i][j][3] * sc;
        }
}

// ---------------------------------------------------------------------------
// Kernel 3: causal row softmax; zero-fills masked tail (lets PV over-read)
// ---------------------------------------------------------------------------
__global__ __launch_bounds__(128) void k_softmax() {
    int r = blockIdx.x;
    int z = blockIdx.y;
    float* row = gS + (size_t)z * T_ * T_ + (size_t)r * T_;
    int n = r + 1;
    int tid = threadIdx.x;
    __shared__ float sm[4];

    float v = -3.4e38f;
    for (int i = tid; i < n; i += 128) v = fmaxf(v, row[i]);
#pragma unroll
    for (int o = 16; o; o >>= 1) v = fmaxf(v, __shfl_xor_sync(0xffffffffu, v, o));
    if ((tid & 31) == 0) sm[tid >> 5] = v;
    __syncthreads();
    float M = fmaxf(fmaxf(sm[0], sm[1]), fmaxf(sm[2], sm[3]));
    __syncthreads();

    float s = 0.f;
    for (int i = tid; i < n; i += 128) {
        float e = __expf(row[i] - M);
        row[i] = e;
        s += e;
    }
#pragma unroll
    for (int o = 16; o; o >>= 1) s += __shfl_xor_sync(0xffffffffu, s, o);
    if ((tid & 31) == 0) sm[tid >> 5] = s;
    __syncthreads();
    float inv = 1.f / (sm[0] + sm[1] + sm[2] + sm[3]);

    for (int i = tid; i < T_; i += 128)
        row[i] = (i < n) ? row[i] * inv : 0.f;
}

// ---------------------------------------------------------------------------
// Kernel 4: O = P V  (K-loop truncated by causality), writes concat layout gY
// ---------------------------------------------------------------------------
__global__ __launch_bounds__(256) void k_av() {
    extern __shared__ __align__(16) uint32_t smem[];
    uint32_t* As = smem;
    uint32_t* Bs = smem + 2 * ASZ;
    int tid = threadIdx.x, lane = tid & 31, wid = tid >> 5;
    int wm = wid >> 2, wn = wid & 3;

    int n0 = blockIdx.x * BN;      // d0
    int m0 = blockIdx.y * BM;      // t0
    int z = blockIdx.z;
    int b = z >> 3, h = z & 7;

    const float* Ag = gS + (size_t)z * T_ * T_ + (size_t)m0 * T_;
    const float* Bg = gV + (size_t)z * T_ * HD_ + n0;
    int nkt = (m0 + BM) / BK;      // causal truncation

    float acc[4][4][4];
    zero_acc(acc);
    gemm_main<false>(Ag, T_, Bg, HD_, nkt, As, Bs, acc, tid, lane, wm, wn);

    float* C = gY + ((size_t)b * T_ + m0) * E_ + h * HD_ + n0;
    store_acc(C, E_, acc, lane, wm, wn);
}

// ---------------------------------------------------------------------------
// Kernel 5: out = Y @ Wo + bo
// ---------------------------------------------------------------------------
__global__ __launch_bounds__(256) void k_out(const float* __restrict__ Wo,
                                             const float* __restrict__ bo,
                                             float* __restrict__ out) {
    extern __shared__ __align__(16) uint32_t smem[];
    uint32_t* As = smem;
    uint32_t* Bs = smem + 2 * ASZ;
    int tid = threadIdx.x, lane = tid & 31, wid = tid >> 5;
    int wm = wid >> 2, wn = wid & 3;

    int n0 = blockIdx.x * BN;
    int m0 = blockIdx.y * BM;

    const float* Ag = gY + (size_t)m0 * E_;
    const float* Bg = Wo + n0;

    float acc[4][4][4];
    zero_acc(acc);
    gemm_main<false>(Ag, E_, Bg, E_, E_ / BK, As, Bs, acc, tid, lane, wm, wn);

    float* C = out + (size_t)m0 * E_ + n0;
    int g = lane >> 2, t = lane & 3;
#pragma unroll
    for (int i = 0; i < 4; i++)
#pragma unroll
        for (int j = 0; j < 4; j++) {
            int r0 = (wm * 4 + i) * 16 + g;
            int c0 = (wn * 4 + j) * 8 + t * 2;
            float b0 = bo[n0 + c0], b1 = bo[n0 + c0 + 1];
            float* p = C + (size_t)r0 * E_ + c0;
            p[0]           = acc[i][j][0] + b0;
            p[1]           = acc[i][j][1] + b1;
            p[8 * E_]      = acc[i][j][2] + b0;
            p[8 * E_ + 1]  = acc[i][j][3] + b1;
        }
}

// ---------------------------------------------------------------------------
extern "C" void kernel_launch(void* const* d_in, const int* in_sizes, int n_in,
                              void* d_out, int out_size) {
    const float* data = (const float*)d_in[0];
    const float* Wq   = (const float*)d_in[1];
    const float* Wk   = (const float*)d_in[2];
    const float* Wv   = (const float*)d_in[3];
    const float* Wo   = (const float*)d_in[4];
    const float* bo   = (const float*)d_in[5];
    float* out = (float*)d_out;

    static int attr_done = 0;
    if (!attr_done) {
        cudaFuncSetAttribute(k_qkv,    cudaFuncAttributeMaxDynamicSharedMemorySize, SMEM_DB);
        cudaFuncSetAttribute(k_scores, cudaFuncAttributeMaxDynamicSharedMemorySize, SMEM_DB);
        cudaFuncSetAttribute(k_av,     cudaFuncAttributeMaxDynamicSharedMemorySize, SMEM_DB);
        cudaFuncSetAttribute(k_out,    cudaFuncAttributeMaxDynamicSharedMemorySize, SMEM_DB);
        attr_done = 1;
    }

    k_qkv   <<<dim3(96, 64),    256, SMEM_DB>>>(data, Wq, Wk, Wv);
    k_scores<<<dim3(4, 4, NBH), 256, SMEM_DB>>>();
    k_softmax<<<dim3(T_, NBH),  128>>>();
    k_av    <<<dim3(4, 4, NBH), 256, SMEM_DB>>>();
    k_out   <<<dim3(32, 64),    256, SMEM_DB>>>(Wo, bo, out);
}